// round 1
// baseline (speedup 1.0000x reference)
#include <cuda_runtime.h>
#include <math.h>

#define BATCH 8
#define WIN   4096
#define RDIM  128
#define DDIM  128
#define BLKSZ 128
#define NBLK  (WIN / BLKSZ)   // 32

// ---------------- scratch (device globals; no allocation allowed) ----------
__device__ float g_pow[(BLKSZ + 1) * RDIM];   // pow[n][r] = gamma_r^n, n=0..128
__device__ float g_ipow[BLKSZ * RDIM];        // ipow[n][r] = gamma_r^{-n}, n=0..127
__device__ float g_S[BATCH * NBLK * RDIM * DDIM];      // per-block local state (i=127 row)
__device__ float g_state[BATCH * NBLK * RDIM * DDIM];  // state entering each block

typedef unsigned long long u64;

// Packed fp32x2 FMA (Blackwell): doubles FFMA issue rate vs reg-reg FFMA (rt 2 -> eff 1)
__device__ __forceinline__ u64 pk2(float lo, float hi) {
    u64 r; asm("mov.b64 %0,{%1,%2};" : "=l"(r) : "f"(lo), "f"(hi)); return r;
}
__device__ __forceinline__ void upk2(u64 v, float& lo, float& hi) {
    asm("mov.b64 {%0,%1},%2;" : "=f"(lo), "=f"(hi) : "l"(v));
}
__device__ __forceinline__ void ffma2(u64& d, u64 a, u64 b) {
    asm("fma.rn.f32x2 %0,%1,%2,%0;" : "+l"(d) : "l"(a), "l"(b));
}

// ---------------- kernel 0: decay power tables ------------------------------
__global__ void pow_kernel(const float* __restrict__ gamma) {
    int r = threadIdx.x;
    float g = gamma[r];
    g = fmaxf(g, 1e-8f);
    float lg = logf(g);
    for (int n = 0; n <= BLKSZ; n++) g_pow[n * RDIM + r] = expf((float)n * lg);
    for (int n = 0; n < BLKSZ; n++)  g_ipow[n * RDIM + r] = expf(-(float)n * lg);
}

// ---------------- kernel 1: S[b,n,r,d] = sum_j gamma^{127-j} k[j,r] h[j,d] ---
// grid 256 (b*NBLK+n), block 256 (16x16 threads, 8x8 outputs each)
__global__ __launch_bounds__(256) void s_kernel(const float* __restrict__ k,
                                                const float* __restrict__ h) {
    __shared__ float sk[16][RDIM + 4];   // scaled k, [jj][r]
    __shared__ float sh[16][DDIM + 4];   // h,        [jj][d]
    int bn = blockIdx.x;
    int b = bn / NBLK, n = bn % NBLK;
    const float* kp = k + ((size_t)b * WIN + (size_t)n * BLKSZ) * RDIM;
    const float* hp = h + ((size_t)b * WIN + (size_t)n * BLKSZ) * DDIM;
    float* Sp = g_S + (size_t)bn * RDIM * DDIM;
    int tid = threadIdx.x, tx = tid & 15, ty = tid >> 4;

    u64 acc[8][4];
#pragma unroll
    for (int u = 0; u < 8; u++)
#pragma unroll
        for (int v = 0; v < 4; v++) acc[u][v] = 0ull;

    for (int j0 = 0; j0 < BLKSZ; j0 += 16) {
#pragma unroll
        for (int t = 0; t < 8; t++) {
            int idx = tid + t * 256;
            int jj = idx >> 7, c = idx & 127;
            int j = j0 + jj;
            sk[jj][c] = kp[(size_t)j * RDIM + c] * g_pow[(127 - j) * RDIM + c];
            sh[jj][c] = hp[(size_t)j * DDIM + c];
        }
        __syncthreads();
#pragma unroll
        for (int jj = 0; jj < 16; jj++) {
            float a[8];
            u64 bb[4];
#pragma unroll
            for (int u = 0; u < 8; u++) a[u] = sk[jj][ty * 8 + u];
#pragma unroll
            for (int v = 0; v < 4; v++) bb[v] = *(const u64*)&sh[jj][tx * 8 + v * 2];
#pragma unroll
            for (int u = 0; u < 8; u++) {
                u64 ap = pk2(a[u], a[u]);
#pragma unroll
                for (int v = 0; v < 4; v++) ffma2(acc[u][v], ap, bb[v]);
            }
        }
        __syncthreads();
    }
#pragma unroll
    for (int u = 0; u < 8; u++) {
        int r = ty * 8 + u;
#pragma unroll
        for (int v = 0; v < 4; v++) {
            float lo, hi; upk2(acc[u][v], lo, hi);
            int d = tx * 8 + v * 2;
            *(float2*)&Sp[(size_t)r * DDIM + d] = make_float2(lo, hi);
        }
    }
}

// ---------------- kernel 2: elementwise scan over blocks --------------------
// state[b,0]=0 ; state[b,n] = gamma^128 * state[b,n-1] + S[b,n-1]
// grid (RDIM, BATCH), block DDIM
__global__ void scan_kernel() {
    int r = blockIdx.x, b = blockIdx.y, d = threadIdx.x;
    float g = g_pow[BLKSZ * RDIM + r];   // gamma_r^128
    float s = 0.f;
    size_t base = ((size_t)b * NBLK) * RDIM * DDIM + (size_t)r * DDIM + d;
    for (int n = 0; n < NBLK; n++) {
        size_t off = base + (size_t)n * RDIM * DDIM;
        g_state[off] = s;
        s = fmaf(g, s, g_S[off]);
    }
}

// ---------------- kernel 3: per-tile output ---------------------------------
// As[j][i] = [j<=i] sum_r (k[j,r] g^-j)(q[i,r] g^i)   (128x128 in smem)
// out[i,d] = sum_j As[j][i] h[j,d]  +  sum_r (q[i,r] g^{i+1}) state[r,d]
// grid 256, block 256, dynamic smem = (128+32)*132*4 = 84480 B
#define AP 132
#define SMEM3_BYTES ((128 + 32) * AP * 4)

__global__ __launch_bounds__(256) void out_kernel(const float* __restrict__ q,
                                                  const float* __restrict__ kk,
                                                  const float* __restrict__ h,
                                                  float* __restrict__ out) {
    extern __shared__ float smem[];
    float* As = smem;               // [128][AP], stored transposed: As[j][i]
    float* tA = smem + 128 * AP;    // [16][AP]
    float* tB = tA + 16 * AP;       // [16][AP]

    int bn = blockIdx.x;
    int b = bn / NBLK, n = bn % NBLK;
    const float* qp = q  + ((size_t)b * WIN + (size_t)n * BLKSZ) * RDIM;
    const float* kp = kk + ((size_t)b * WIN + (size_t)n * BLKSZ) * RDIM;
    const float* hp = h  + ((size_t)b * WIN + (size_t)n * BLKSZ) * DDIM;
    const float* st = g_state + (size_t)bn * RDIM * DDIM;
    float* op = out + ((size_t)b * WIN + (size_t)n * BLKSZ) * DDIM;
    int tid = threadIdx.x, tx = tid & 15, ty = tid >> 4;

    u64 acc[8][4];
#pragma unroll
    for (int u = 0; u < 8; u++)
#pragma unroll
        for (int v = 0; v < 4; v++) acc[u][v] = 0ull;

    // ---- Phase 1: build A^T (rows = j via ty, cols = i via tx) ----
    for (int r0 = 0; r0 < RDIM; r0 += 16) {
#pragma unroll
        for (int t = 0; t < 8; t++) {
            int idx = tid + t * 256;
            int rr = idx & 15, x = idx >> 4;           // x = j or i (0..127)
            int rc = r0 + rr;
            tA[rr * AP + x] = kp[(size_t)x * RDIM + rc] * g_ipow[x * RDIM + rc];
            tB[rr * AP + x] = qp[(size_t)x * RDIM + rc] * g_pow[x * RDIM + rc];
        }
        __syncthreads();
#pragma unroll
        for (int rr = 0; rr < 16; rr++) {
            float a[8];
            u64 bb[4];
#pragma unroll
            for (int u = 0; u < 8; u++) a[u] = tA[rr * AP + ty * 8 + u];
#pragma unroll
            for (int v = 0; v < 4; v++) bb[v] = *(const u64*)&tB[rr * AP + tx * 8 + v * 2];
#pragma unroll
            for (int u = 0; u < 8; u++) {
                u64 ap = pk2(a[u], a[u]);
#pragma unroll
                for (int v = 0; v < 4; v++) ffma2(acc[u][v], ap, bb[v]);
            }
        }
        __syncthreads();
    }
    // masked write: keep j <= i
#pragma unroll
    for (int u = 0; u < 8; u++) {
        int j = ty * 8 + u;
#pragma unroll
        for (int v = 0; v < 4; v++) {
            float lo, hi; upk2(acc[u][v], lo, hi);
            int i0 = tx * 8 + v * 2;
            As[j * AP + i0]     = (j <= i0)     ? lo : 0.f;
            As[j * AP + i0 + 1] = (j <= i0 + 1) ? hi : 0.f;
        }
    }
    __syncthreads();

    // ---- Phase 2: out = A @ h (rows = i via ty, cols = d via tx) ----
#pragma unroll
    for (int u = 0; u < 8; u++)
#pragma unroll
        for (int v = 0; v < 4; v++) acc[u][v] = 0ull;

    for (int j0 = 0; j0 < BLKSZ; j0 += 16) {
#pragma unroll
        for (int t = 0; t < 8; t++) {
            int idx = tid + t * 256;
            int jj = idx >> 7, d = idx & 127;
            tB[jj * AP + d] = hp[(size_t)(j0 + jj) * DDIM + d];
        }
        __syncthreads();
#pragma unroll
        for (int jj = 0; jj < 16; jj++) {
            float a[8];
            u64 bb[4];
#pragma unroll
            for (int u = 0; u < 8; u++) a[u] = As[(j0 + jj) * AP + ty * 8 + u];
#pragma unroll
            for (int v = 0; v < 4; v++) bb[v] = *(const u64*)&tB[jj * AP + tx * 8 + v * 2];
#pragma unroll
            for (int u = 0; u < 8; u++) {
                u64 ap = pk2(a[u], a[u]);
#pragma unroll
                for (int v = 0; v < 4; v++) ffma2(acc[u][v], ap, bb[v]);
            }
        }
        __syncthreads();
    }

    // ---- Phase 3: out += (q * gamma^{i+1}) @ state ----
    for (int r0 = 0; r0 < RDIM; r0 += 16) {
#pragma unroll
        for (int t = 0; t < 8; t++) {
            int idx = tid + t * 256;
            {   // carry weights, [rr][i]
                int rr = idx & 15, i = idx >> 4;
                int rc = r0 + rr;
                tA[rr * AP + i] = qp[(size_t)i * RDIM + rc] * g_pow[(i + 1) * RDIM + rc];
            }
            {   // state tile, [rr][d]
                int rr = idx >> 7, d = idx & 127;
                tB[rr * AP + d] = st[(size_t)(r0 + rr) * DDIM + d];
            }
        }
        __syncthreads();
#pragma unroll
        for (int rr = 0; rr < 16; rr++) {
            float a[8];
            u64 bb[4];
#pragma unroll
            for (int u = 0; u < 8; u++) a[u] = tA[rr * AP + ty * 8 + u];
#pragma unroll
            for (int v = 0; v < 4; v++) bb[v] = *(const u64*)&tB[rr * AP + tx * 8 + v * 2];
#pragma unroll
            for (int u = 0; u < 8; u++) {
                u64 ap = pk2(a[u], a[u]);
#pragma unroll
                for (int v = 0; v < 4; v++) ffma2(acc[u][v], ap, bb[v]);
            }
        }
        __syncthreads();
    }

    // ---- store ----
#pragma unroll
    for (int u = 0; u < 8; u++) {
        int i = ty * 8 + u;
#pragma unroll
        for (int v = 0; v < 4; v++) {
            float lo, hi; upk2(acc[u][v], lo, hi);
            int d = tx * 8 + v * 2;
            *(float2*)&op[(size_t)i * DDIM + d] = make_float2(lo, hi);
        }
    }
}

// ---------------- launch ----------------------------------------------------
extern "C" void kernel_launch(void* const* d_in, const int* in_sizes, int n_in,
                              void* d_out, int out_size) {
    const float* q     = (const float*)d_in[0];   // [B,W,R]
    const float* k     = (const float*)d_in[1];   // [B,W,R]
    const float* h     = (const float*)d_in[2];   // [B,W,D]
    const float* gamma = (const float*)d_in[3];   // [R]
    float* out = (float*)d_out;                   // [B,W,D]

    cudaFuncSetAttribute(out_kernel, cudaFuncAttributeMaxDynamicSharedMemorySize,
                         SMEM3_BYTES);

    pow_kernel<<<1, RDIM>>>(gamma);
    s_kernel<<<BATCH * NBLK, 256>>>(k, h);
    scan_kernel<<<dim3(RDIM, BATCH), DDIM>>>();
    out_kernel<<<BATCH * NBLK, 256, SMEM3_BYTES>>>(q, k, h, out);
}

// round 3
// speedup vs baseline: 1.3787x; 1.3787x over previous
#include <cuda_runtime.h>
#include <cuda_bf16.h>
#include <math.h>
#include <stdint.h>

#define BATCH 8
#define WIN   4096
#define RDIM  128
#define DDIM  128
#define BLKSZ 128
#define NBLK  (WIN / BLKSZ)   // 32
#define NTILE (BATCH * NBLK)  // 256

// ---------------- scratch (device globals; no allocation allowed) ----------
__device__ float g_pow[(BLKSZ + 1) * RDIM];   // pow[n][r] = gamma_r^n
__device__ float g_ipow[BLKSZ * RDIM];        // ipow[n][r] = gamma_r^{-n}
__device__ float g_S[NTILE * RDIM * DDIM];    // per-block local chunk state
__device__ float g_state[NTILE * RDIM * DDIM];// carry state entering each block

// ---------------- smem matrix layout ----------------------------------------
// split bf16 matrix: hi half then lo half; each half 128 rows x 136 bf16
// (row stride 68 words -> 68 mod 32 = 4 -> fragment loads are bank-conflict-free)
#define SROW_W 68
#define HALF_W (128 * SROW_W)     // 8704 words
#define MAT_W  (2 * HALF_W)       // 17408 words = 69632 bytes

#define STG_F  (16 * 132)         // fp32 staging for transpose: 8448 bytes

#define O_SMEM_BYTES (3 * MAT_W * 4 + STG_F * 4)   // 217,344
#define S_SMEM_BYTES (2 * MAT_W * 4 + STG_F * 4)   // 147,712

// ---------------- helpers ----------------------------------------------------
__device__ __forceinline__ uint32_t pkbf(float a, float b) {
    __nv_bfloat162 t = __floats2bfloat162_rn(a, b);
    return *reinterpret_cast<uint32_t*>(&t);
}
__device__ __forceinline__ void split1(float v, float& hi, float& lo) {
    __nv_bfloat16 h = __float2bfloat16(v);
    hi = __bfloat162float(h);
    lo = v - hi;
}
__device__ __forceinline__ void mma_bf16(float* c, const uint32_t* a, const uint32_t* b) {
    asm volatile(
        "mma.sync.aligned.m16n8k16.row.col.f32.bf16.bf16.f32 "
        "{%0,%1,%2,%3}, {%4,%5,%6,%7}, {%8,%9}, {%0,%1,%2,%3};"
        : "+f"(c[0]), "+f"(c[1]), "+f"(c[2]), "+f"(c[3])
        : "r"(a[0]), "r"(a[1]), "r"(a[2]), "r"(a[3]), "r"(b[0]), "r"(b[1]));
}

// A fragment (m16k16, row-major) from one split-half; rows mrow..mrow+15
__device__ __forceinline__ void ldA(uint32_t* a, const uint32_t* half,
                                    int mrow, int kt, int lane) {
    int g = lane >> 2, tc = lane & 3;
    const uint32_t* p = half + (mrow + g) * SROW_W + kt * 8 + tc;
    a[0] = p[0];
    a[2] = p[4];
    p += 8 * SROW_W;
    a[1] = p[0];
    a[3] = p[4];
}
// B fragment (k16n8, col-major) from memory laid out [n][k]
__device__ __forceinline__ void ldB(uint32_t* b, const uint32_t* half,
                                    int nt, int kt, int lane) {
    int g = lane >> 2, tc = lane & 3;
    const uint32_t* p = half + (nt * 8 + g) * SROW_W + kt * 8 + tc;
    b[0] = p[0];
    b[1] = p[4];
}

// scale+split+store, natural layout: mat[row i][col c] = src[i][c] * scl[i][c]
__device__ __forceinline__ void build_nat(const float* __restrict__ src,
                                          const float* __restrict__ scl,
                                          uint32_t* __restrict__ mat, int tid) {
#pragma unroll 4
    for (int p = tid; p < 8192; p += 256) {
        int i = p >> 6, cp = p & 63;
        float2 v = *reinterpret_cast<const float2*>(src + i * 128 + cp * 2);
        float2 s = *reinterpret_cast<const float2*>(scl + i * 128 + cp * 2);
        float v0 = v.x * s.x, v1 = v.y * s.y;
        float h0, l0, h1, l1;
        split1(v0, h0, l0);
        split1(v1, h1, l1);
        int w = i * SROW_W + cp;
        mat[w] = pkbf(h0, h1);
        mat[w + HALF_W] = pkbf(l0, l1);
    }
}

// scale+split+store, transposed: mat[row c][col j] = src[j][c] * sclp[j*sstride + c]
__device__ __forceinline__ void build_tr(const float* __restrict__ src,
                                         const float* __restrict__ sclp, int sstride,
                                         float* __restrict__ stg,
                                         uint32_t* __restrict__ mat, int tid) {
    for (int j0 = 0; j0 < 128; j0 += 16) {
#pragma unroll
        for (int u = 0; u < 8; u++) {
            int idx = tid + u * 256;
            int jj = idx >> 7, c = idx & 127;
            float v = src[(j0 + jj) * 128 + c];
            if (sclp) v *= sclp[(j0 + jj) * sstride + c];
            stg[jj * 132 + c] = v;
        }
        __syncthreads();
        int cp = tid & 127;
        int mb = (tid >> 7) * 4;
#pragma unroll
        for (int u = 0; u < 4; u++) {
            int jc = 2 * (mb + u);
            float v0 = stg[jc * 132 + cp];
            float v1 = stg[(jc + 1) * 132 + cp];
            float h0, l0, h1, l1;
            split1(v0, h0, l0);
            split1(v1, h1, l1);
            int w = cp * SROW_W + (j0 + jc) / 2;
            mat[w] = pkbf(h0, h1);
            mat[w + HALF_W] = pkbf(l0, l1);
        }
        __syncthreads();
    }
}

// C[16][4] += A(smem split) * B(smem split)^T  -- fp32-emulated via 3 bf16 terms
__device__ __forceinline__ void gemm_ss(float C[16][4], const uint32_t* A,
                                        const uint32_t* B, int mrow, int lane) {
#pragma unroll 1
    for (int kt = 0; kt < 8; kt++) {
        uint32_t ah[4], al[4];
        ldA(ah, A, mrow, kt, lane);
        ldA(al, A + HALF_W, mrow, kt, lane);
#pragma unroll
        for (int nt = 0; nt < 16; nt++) {
            uint32_t bh[2], bl[2];
            ldB(bh, B, nt, kt, lane);
            ldB(bl, B + HALF_W, nt, kt, lane);
            mma_bf16(C[nt], ah, bh);
            mma_bf16(C[nt], ah, bl);
            mma_bf16(C[nt], al, bh);
        }
    }
}

// ---------------- kernel 0: decay power tables (parallel over n) -----------
__global__ void pow_kernel(const float* __restrict__ gamma) {
    int n = blockIdx.x;          // 0..128
    int r = threadIdx.x;
    float g = fmaxf(gamma[r], 1e-8f);
    float lg = logf(g);
    g_pow[n * RDIM + r] = expf((float)n * lg);
    if (n < BLKSZ) g_ipow[n * RDIM + r] = expf(-(float)n * lg);
}

// ---------------- kernel 1: S[r,d] = sum_j gamma^{127-j} k[j,r] h[j,d] ------
__global__ __launch_bounds__(256, 1)
void s_kernel(const float* __restrict__ k, const float* __restrict__ h) {
    extern __shared__ uint32_t smw[];
    uint32_t* M0 = smw;                 // k2^T  [r][j]
    uint32_t* M1 = smw + MAT_W;         // h^T   [d][j]
    float* stg = (float*)(smw + 2 * MAT_W);

    int tid = threadIdx.x;
    int lane = tid & 31, wid = tid >> 5;
    int wrow = wid * 16;
    int bn = blockIdx.x;
    int b = bn / NBLK, n = bn % NBLK;
    const float* kp = k + ((size_t)b * WIN + (size_t)n * BLKSZ) * RDIM;
    const float* hp = h + ((size_t)b * WIN + (size_t)n * BLKSZ) * DDIM;
    float* Sp = g_S + (size_t)bn * RDIM * DDIM;

    // A[r][j] = k[j][r] * gamma_r^{127-j}
    build_tr(kp, g_pow + 127 * RDIM, -RDIM, stg, M0, tid);
    // B mem [d][j] = h[j][d]
    build_tr(hp, (const float*)0, 0, stg, M1, tid);
    __syncthreads();

    float C[16][4];
#pragma unroll
    for (int nt = 0; nt < 16; nt++)
#pragma unroll
        for (int v = 0; v < 4; v++) C[nt][v] = 0.f;

    gemm_ss(C, M0, M1, wrow, lane);

    int g = lane >> 2, tc = lane & 3;
#pragma unroll
    for (int nt = 0; nt < 16; nt++) {
        int d0 = nt * 8 + tc * 2;
        *reinterpret_cast<float2*>(Sp + (wrow + g) * 128 + d0) =
            make_float2(C[nt][0], C[nt][1]);
        *reinterpret_cast<float2*>(Sp + (wrow + g + 8) * 128 + d0) =
            make_float2(C[nt][2], C[nt][3]);
    }
}

// ---------------- kernel 2: elementwise scan over blocks --------------------
__global__ void scan_kernel() {
    int r = blockIdx.x, b = blockIdx.y, d = threadIdx.x;
    float g = g_pow[BLKSZ * RDIM + r];   // gamma_r^128
    float s = 0.f;
    size_t base = ((size_t)b * NBLK) * RDIM * DDIM + (size_t)r * DDIM + d;
#pragma unroll 4
    for (int n = 0; n < NBLK; n++) {
        size_t off = base + (size_t)n * RDIM * DDIM;
        g_state[off] = s;
        s = fmaf(g, s, g_S[off]);
    }
}

// ---------------- kernel 3: per-tile output ---------------------------------
// P = (q g^i)(k g^-j)^T  (causal-masked, kept in registers)
// out = P @ H + (q g^{i+1}) @ state
__global__ __launch_bounds__(256, 1)
void out_kernel(const float* __restrict__ q, const float* __restrict__ kk,
                const float* __restrict__ h, float* __restrict__ out) {
    extern __shared__ uint32_t smw[];
    uint32_t* M0 = smw;                 // Qhat, later Qtilde  [i][r]
    uint32_t* M1 = smw + MAT_W;         // Khat, later state^T
    uint32_t* M2 = smw + 2 * MAT_W;     // H^T  [d][j]
    float* stg = (float*)(smw + 3 * MAT_W);

    int tid = threadIdx.x;
    int lane = tid & 31, wid = tid >> 5;
    int wrow = wid * 16;
    int g = lane >> 2, tc = lane & 3;
    int bn = blockIdx.x;
    int b = bn / NBLK, n = bn % NBLK;
    const float* qp = q  + ((size_t)b * WIN + (size_t)n * BLKSZ) * RDIM;
    const float* kp = kk + ((size_t)b * WIN + (size_t)n * BLKSZ) * RDIM;
    const float* hp = h  + ((size_t)b * WIN + (size_t)n * BLKSZ) * DDIM;
    const float* st = g_state + (size_t)bn * RDIM * DDIM;
    float* op = out + ((size_t)b * WIN + (size_t)n * BLKSZ) * DDIM;

    // ---- build Qhat = q*g^i, Khat = k*g^-j, H^T --------------------------
    build_nat(qp, g_pow, M0, tid);
    build_nat(kp, g_ipow, M1, tid);
    build_tr(hp, (const float*)0, 0, stg, M2, tid);
    __syncthreads();

    // ---- GEMM1: P = Qhat @ Khat^T ----------------------------------------
    float P[16][4];
#pragma unroll
    for (int nt = 0; nt < 16; nt++)
#pragma unroll
        for (int v = 0; v < 4; v++) P[nt][v] = 0.f;
    gemm_ss(P, M0, M1, wrow, lane);

    // ---- causal mask + split into A-fragments (registers only) -----------
    uint32_t pah[8][4], pal[8][4];
#pragma unroll
    for (int nt = 0; nt < 16; nt++) {
        int jb = nt * 8 + tc * 2;
        int i0 = wrow + g, i1 = wrow + g + 8;
        float c0 = (jb     <= i0) ? P[nt][0] : 0.f;
        float c1 = (jb + 1 <= i0) ? P[nt][1] : 0.f;
        float c2 = (jb     <= i1) ? P[nt][2] : 0.f;
        float c3 = (jb + 1 <= i1) ? P[nt][3] : 0.f;
        float h0, l0, h1, l1, h2, l2, h3, l3;
        split1(c0, h0, l0);
        split1(c1, h1, l1);
        split1(c2, h2, l2);
        split1(c3, h3, l3);
        int kt = nt >> 1, s = (nt & 1) * 2;
        pah[kt][s]     = pkbf(h0, h1);
        pah[kt][s + 1] = pkbf(h2, h3);
        pal[kt][s]     = pkbf(l0, l1);
        pal[kt][s + 1] = pkbf(l2, l3);
    }

    // ---- GEMM2: C = P @ H  (A from registers, B = H^T in smem) -----------
    float C[16][4];
#pragma unroll
    for (int nt = 0; nt < 16; nt++)
#pragma unroll
        for (int v = 0; v < 4; v++) C[nt][v] = 0.f;
#pragma unroll 1
    for (int kt = 0; kt < 8; kt++) {
#pragma unroll
        for (int nt = 0; nt < 16; nt++) {
            uint32_t bh[2], bl[2];
            ldB(bh, M2, nt, kt, lane);
            ldB(bl, M2 + HALF_W, nt, kt, lane);
            mma_bf16(C[nt], pah[kt], bh);
            mma_bf16(C[nt], pah[kt], bl);
            mma_bf16(C[nt], pal[kt], bh);
        }
    }

    // ---- rebuild: Qtilde = q*g^{i+1} in M0, state^T in M1 ----------------
    __syncthreads();
    build_nat(qp, g_pow + RDIM, M0, tid);
    build_tr(st, (const float*)0, 0, stg, M1, tid);
    __syncthreads();

    // ---- GEMM3: C += Qtilde @ state --------------------------------------
    gemm_ss(C, M0, M1, wrow, lane);

    // ---- store ------------------------------------------------------------
#pragma unroll
    for (int nt = 0; nt < 16; nt++) {
        int d0 = nt * 8 + tc * 2;
        *reinterpret_cast<float2*>(op + (wrow + g) * 128 + d0) =
            make_float2(C[nt][0], C[nt][1]);
        *reinterpret_cast<float2*>(op + (wrow + g + 8) * 128 + d0) =
            make_float2(C[nt][2], C[nt][3]);
    }
}

// ---------------- launch ----------------------------------------------------
extern "C" void kernel_launch(void* const* d_in, const int* in_sizes, int n_in,
                              void* d_out, int out_size) {
    const float* q     = (const float*)d_in[0];   // [B,W,R]
    const float* k     = (const float*)d_in[1];   // [B,W,R]
    const float* h     = (const float*)d_in[2];   // [B,W,D]
    const float* gamma = (const float*)d_in[3];   // [R]
    float* out = (float*)d_out;                   // [B,W,D]

    cudaFuncSetAttribute(s_kernel, cudaFuncAttributeMaxDynamicSharedMemorySize,
                         S_SMEM_BYTES);
    cudaFuncSetAttribute(out_kernel, cudaFuncAttributeMaxDynamicSharedMemorySize,
                         O_SMEM_BYTES);

    pow_kernel<<<BLKSZ + 1, RDIM>>>(gamma);
    s_kernel<<<NTILE, 256, S_SMEM_BYTES>>>(k, h);
    scan_kernel<<<dim3(RDIM, BATCH), DDIM>>>();
    out_kernel<<<NTILE, 256, O_SMEM_BYTES>>>(q, k, h, out);
}

// round 4
// speedup vs baseline: 2.1242x; 1.5407x over previous
#include <cuda_runtime.h>
#include <cuda_bf16.h>
#include <math.h>
#include <stdint.h>

#define BATCH 8
#define WIN   4096
#define RDIM  128
#define DDIM  128
#define BLKSZ 128
#define NBLK  (WIN / BLKSZ)   // 32
#define NTILE (BATCH * NBLK)  // 256

// ---------------- scratch (device globals) ----------------------------------
__device__ float g_pow[(BLKSZ + 1) * RDIM];   // pow[n][r] = gamma_r^n
__device__ float g_ipow[BLKSZ * RDIM];        // ipow[n][r] = gamma_r^{-n}
__device__ float g_S[NTILE * RDIM * DDIM];
__device__ float g_state[NTILE * RDIM * DDIM];

// ---------------- smem matrix layout -----------------------------------------
// split bf16 matrix: hi half then lo half; each half 128 rows x 136 bf16
// row stride 68 words (68 mod 32 = 4 -> conflict-free fragment loads)
#define SROW_W 68
#define HALF_W (128 * SROW_W)
#define MAT_W  (2 * HALF_W)               // 17408 words = 69632 B
#define STG_F  (16 * 132)                 // 8448 B staging
#define SMEM_BYTES (MAT_W * 4 + STG_F * 4)  // 78080 B -> 2 CTAs/SM

// ---------------- helpers ----------------------------------------------------
__device__ __forceinline__ uint32_t pkbf(float a, float b) {
    __nv_bfloat162 t = __floats2bfloat162_rn(a, b);
    return *reinterpret_cast<uint32_t*>(&t);
}
__device__ __forceinline__ void split1(float v, float& hi, float& lo) {
    __nv_bfloat16 h = __float2bfloat16(v);
    hi = __bfloat162float(h);
    lo = v - hi;
}
// split a float pair into packed hi-pair and lo-pair
__device__ __forceinline__ void split2(float a, float b, uint32_t& ph, uint32_t& pl) {
    float h0, l0, h1, l1;
    split1(a, h0, l0);
    split1(b, h1, l1);
    ph = pkbf(h0, h1);
    pl = pkbf(l0, l1);
}
__device__ __forceinline__ void mma_bf16(float* c, const uint32_t* a, const uint32_t* b) {
    asm volatile(
        "mma.sync.aligned.m16n8k16.row.col.f32.bf16.bf16.f32 "
        "{%0,%1,%2,%3}, {%4,%5,%6,%7}, {%8,%9}, {%0,%1,%2,%3};"
        : "+f"(c[0]), "+f"(c[1]), "+f"(c[2]), "+f"(c[3])
        : "r"(a[0]), "r"(a[1]), "r"(a[2]), "r"(a[3]), "r"(b[0]), "r"(b[1]));
}
// B fragment (k16n8 col-major) from smem laid out [n][k] (split half base)
__device__ __forceinline__ void ldB(uint32_t* b, const uint32_t* half,
                                    int nt, int kt, int lane) {
    int g = lane >> 2, tc = lane & 3;
    const uint32_t* p = half + (nt * 8 + g) * SROW_W + kt * 8 + tc;
    b[0] = p[0];
    b[1] = p[4];
}

// A fragment streamed from global, natural layout: A[i][r] = src[i][r]*scl[i][r]
// base/sclb already offset to this warp's first row.
__device__ __forceinline__ void ldA_nat(uint32_t* ah, uint32_t* al,
                                        const float* base, const float* sclb,
                                        int kt, int lane) {
    int g = lane >> 2, tc = lane & 3;
    int c = kt * 16 + tc * 2;
    const float* p = base + g * 128 + c;
    const float* w = sclb + g * 128 + c;
    float2 v0 = *(const float2*)(p);
    float2 s0 = *(const float2*)(w);
    float2 v1 = *(const float2*)(p + 8);
    float2 s1 = *(const float2*)(w + 8);
    float2 v2 = *(const float2*)(p + 8 * 128);
    float2 s2 = *(const float2*)(w + 8 * 128);
    float2 v3 = *(const float2*)(p + 8 * 128 + 8);
    float2 s3 = *(const float2*)(w + 8 * 128 + 8);
    split2(v0.x * s0.x, v0.y * s0.y, ah[0], al[0]);
    split2(v2.x * s2.x, v2.y * s2.y, ah[1], al[1]);
    split2(v1.x * s1.x, v1.y * s1.y, ah[2], al[2]);
    split2(v3.x * s3.x, v3.y * s3.y, ah[3], al[3]);
}

// A fragment streamed from global, transposed+scaled (s_kernel):
// A[r][j] = k[j*128 + r] * g_pow[(127-j)*128 + r]
__device__ __forceinline__ float ktr_elem(const float* kb, int j, int r) {
    return kb[j * 128 + r] * g_pow[(127 - j) * 128 + r];
}
__device__ __forceinline__ void ldA_ktr(uint32_t* ah, uint32_t* al,
                                        const float* kb, int mrow, int kt, int lane) {
    int g = lane >> 2, tc = lane & 3;
    int r = mrow + g;
    int j = kt * 16 + tc * 2;
    split2(ktr_elem(kb, j,     r),     ktr_elem(kb, j + 1, r),     ah[0], al[0]);
    split2(ktr_elem(kb, j,     r + 8), ktr_elem(kb, j + 1, r + 8), ah[1], al[1]);
    split2(ktr_elem(kb, j + 8, r),     ktr_elem(kb, j + 9, r),     ah[2], al[2]);
    split2(ktr_elem(kb, j + 8, r + 8), ktr_elem(kb, j + 9, r + 8), ah[3], al[3]);
}

// scale+split+store to smem, natural layout (for B operands stored [n][k])
__device__ __forceinline__ void build_nat(const float* __restrict__ src,
                                          const float* __restrict__ scl,
                                          uint32_t* __restrict__ mat, int tid) {
#pragma unroll 4
    for (int p = tid; p < 8192; p += 256) {
        int i = p >> 6, cp = p & 63;
        float2 v = *reinterpret_cast<const float2*>(src + i * 128 + cp * 2);
        float2 s = *reinterpret_cast<const float2*>(scl + i * 128 + cp * 2);
        uint32_t ph, pl;
        split2(v.x * s.x, v.y * s.y, ph, pl);
        int w = i * SROW_W + cp;
        mat[w] = ph;
        mat[w + HALF_W] = pl;
    }
}

// transpose+split+store: mat[row c][col j] = src[j][c]
__device__ __forceinline__ void build_tr(const float* __restrict__ src,
                                         float* __restrict__ stg,
                                         uint32_t* __restrict__ mat, int tid) {
    for (int j0 = 0; j0 < 128; j0 += 16) {
#pragma unroll
        for (int u = 0; u < 8; u++) {
            int idx = tid + u * 256;
            int jj = idx >> 7, c = idx & 127;
            stg[jj * 132 + c] = src[(j0 + jj) * 128 + c];
        }
        __syncthreads();
        int cp = tid & 127;
        int mb = (tid >> 7) * 4;
#pragma unroll
        for (int u = 0; u < 4; u++) {
            int jc = 2 * (mb + u);
            uint32_t ph, pl;
            split2(stg[jc * 132 + cp], stg[(jc + 1) * 132 + cp], ph, pl);
            int w = cp * SROW_W + (j0 + jc) / 2;
            mat[w] = ph;
            mat[w + HALF_W] = pl;
        }
        __syncthreads();
    }
}

// ---------------- kernel 0: decay power tables ------------------------------
__global__ void pow_kernel(const float* __restrict__ gamma) {
    int n = blockIdx.x;
    int r = threadIdx.x;
    float g = fmaxf(gamma[r], 1e-8f);
    float lg = logf(g);
    g_pow[n * RDIM + r] = expf((float)n * lg);
    if (n < BLKSZ) g_ipow[n * RDIM + r] = expf(-(float)n * lg);
}

// ---------------- kernel 1: S[r,d] = sum_j gamma^{127-j} k[j,r] h[j,d] ------
__global__ __launch_bounds__(256, 2)
void s_kernel(const float* __restrict__ k, const float* __restrict__ h) {
    extern __shared__ uint32_t smw[];
    uint32_t* M = smw;                     // H^T [d][j]
    float* stg = (float*)(smw + MAT_W);

    int tid = threadIdx.x;
    int lane = tid & 31, wid = tid >> 5;
    int wrow = wid * 16;
    int bn = blockIdx.x;
    int b = bn / NBLK, n = bn % NBLK;
    const float* kp = k + ((size_t)b * WIN + (size_t)n * BLKSZ) * RDIM;
    const float* hp = h + ((size_t)b * WIN + (size_t)n * BLKSZ) * DDIM;
    float* Sp = g_S + (size_t)bn * RDIM * DDIM;

    build_tr(hp, stg, M, tid);
    __syncthreads();

    float C[16][4];
#pragma unroll
    for (int nt = 0; nt < 16; nt++)
#pragma unroll
        for (int v = 0; v < 4; v++) C[nt][v] = 0.f;

#pragma unroll 2
    for (int kt = 0; kt < 8; kt++) {
        uint32_t ah[4], al[4];
        ldA_ktr(ah, al, kp, wrow, kt, lane);
#pragma unroll
        for (int nt = 0; nt < 16; nt++) {
            uint32_t bh[2], bl[2];
            ldB(bh, M, nt, kt, lane);
            ldB(bl, M + HALF_W, nt, kt, lane);
            mma_bf16(C[nt], ah, bh);
            mma_bf16(C[nt], ah, bl);
            mma_bf16(C[nt], al, bh);
        }
    }

    int g = lane >> 2, tc = lane & 3;
#pragma unroll
    for (int nt = 0; nt < 16; nt++) {
        int d0 = nt * 8 + tc * 2;
        *reinterpret_cast<float2*>(Sp + (wrow + g) * 128 + d0) =
            make_float2(C[nt][0], C[nt][1]);
        *reinterpret_cast<float2*>(Sp + (wrow + g + 8) * 128 + d0) =
            make_float2(C[nt][2], C[nt][3]);
    }
}

// ---------------- kernel 2: elementwise scan over blocks --------------------
__global__ void scan_kernel() {
    int r = blockIdx.x, b = blockIdx.y, d = threadIdx.x;
    float g = g_pow[BLKSZ * RDIM + r];
    float s = 0.f;
    size_t base = ((size_t)b * NBLK) * RDIM * DDIM + (size_t)r * DDIM + d;
#pragma unroll 4
    for (int n = 0; n < NBLK; n++) {
        size_t off = base + (size_t)n * RDIM * DDIM;
        g_state[off] = s;
        s = fmaf(g, s, g_S[off]);
    }
}

// ---------------- kernel 3: per-tile output ---------------------------------
__global__ __launch_bounds__(256, 2)
void out_kernel(const float* __restrict__ q, const float* __restrict__ kk,
                const float* __restrict__ h, float* __restrict__ out) {
    extern __shared__ uint32_t smw[];
    uint32_t* M = smw;                     // Khat -> H^T -> state^T
    float* stg = (float*)(smw + MAT_W);

    int tid = threadIdx.x;
    int lane = tid & 31, wid = tid >> 5;
    int wrow = wid * 16;
    int g = lane >> 2, tc = lane & 3;
    int bn = blockIdx.x;
    int b = bn / NBLK, n = bn % NBLK;
    const float* qp = q  + ((size_t)b * WIN + (size_t)n * BLKSZ) * RDIM;
    const float* kp = kk + ((size_t)b * WIN + (size_t)n * BLKSZ) * RDIM;
    const float* hp = h  + ((size_t)b * WIN + (size_t)n * BLKSZ) * DDIM;
    const float* st = g_state + (size_t)bn * RDIM * DDIM;
    float* op = out + ((size_t)b * WIN + (size_t)n * BLKSZ) * DDIM;

    const float* qwp = qp + wrow * 128;              // warp's q rows
    const float* pw0 = g_pow + wrow * RDIM;          // gamma^i rows
    const float* pw1 = g_pow + (wrow + 1) * RDIM;    // gamma^{i+1} rows

    // ---- build Khat = k * g^-j into M ------------------------------------
    build_nat(kp, g_ipow, M, tid);
    __syncthreads();

    // ---- GEMM1: P = Qhat @ Khat^T  (A streamed from global) --------------
    // causal skip: warp rows <= wrow+15 -> only nt with nt*8 <= wrow+15
    float P[16][4];
#pragma unroll
    for (int nt = 0; nt < 16; nt++)
#pragma unroll
        for (int v = 0; v < 4; v++) P[nt][v] = 0.f;

    int ntmax = 2 * wid + 1;   // inclusive
#pragma unroll 2
    for (int kt = 0; kt < 8; kt++) {
        uint32_t ah[4], al[4];
        ldA_nat(ah, al, qwp, pw0, kt, lane);
#pragma unroll
        for (int nt = 0; nt < 16; nt++) {
            if (nt > ntmax) break;
            uint32_t bh[2], bl[2];
            ldB(bh, M, nt, kt, lane);
            ldB(bl, M + HALF_W, nt, kt, lane);
            mma_bf16(P[nt], ah, bh);
            mma_bf16(P[nt], ah, bl);
            mma_bf16(P[nt], al, bh);
        }
    }

    // ---- causal mask + split P into A-fragments (registers) --------------
    uint32_t pah[8][4], pal[8][4];
#pragma unroll
    for (int nt = 0; nt < 16; nt++) {
        int jb = nt * 8 + tc * 2;
        int i0 = wrow + g, i1 = i0 + 8;
        float c0 = (jb     <= i0) ? P[nt][0] : 0.f;
        float c1 = (jb + 1 <= i0) ? P[nt][1] : 0.f;
        float c2 = (jb     <= i1) ? P[nt][2] : 0.f;
        float c3 = (jb + 1 <= i1) ? P[nt][3] : 0.f;
        int kt = nt >> 1, s = (nt & 1) * 2;
        split2(c0, c1, pah[kt][s],     pal[kt][s]);
        split2(c2, c3, pah[kt][s + 1], pal[kt][s + 1]);
    }

    // ---- rebuild M <- H^T -------------------------------------------------
    __syncthreads();
    build_tr(hp, stg, M, tid);
    __syncthreads();

    // ---- GEMM2: C = P @ H  (A regs, B smem); skip kt > wid ---------------
    float C[16][4];
#pragma unroll
    for (int nt = 0; nt < 16; nt++)
#pragma unroll
        for (int v = 0; v < 4; v++) C[nt][v] = 0.f;
#pragma unroll
    for (int kt = 0; kt < 8; kt++) {
        if (kt > wid) break;
#pragma unroll
        for (int nt = 0; nt < 16; nt++) {
            uint32_t bh[2], bl[2];
            ldB(bh, M, nt, kt, lane);
            ldB(bl, M + HALF_W, nt, kt, lane);
            mma_bf16(C[nt], pah[kt], bh);
            mma_bf16(C[nt], pah[kt], bl);
            mma_bf16(C[nt], pal[kt], bh);
        }
    }

    // ---- rebuild M <- state^T --------------------------------------------
    __syncthreads();
    build_tr(st, stg, M, tid);
    __syncthreads();

    // ---- GEMM3: C += Qtilde @ state  (A streamed, scale gamma^{i+1}) -----
#pragma unroll 2
    for (int kt = 0; kt < 8; kt++) {
        uint32_t ah[4], al[4];
        ldA_nat(ah, al, qwp, pw1, kt, lane);
#pragma unroll
        for (int nt = 0; nt < 16; nt++) {
            uint32_t bh[2], bl[2];
            ldB(bh, M, nt, kt, lane);
            ldB(bl, M + HALF_W, nt, kt, lane);
            mma_bf16(C[nt], ah, bh);
            mma_bf16(C[nt], ah, bl);
            mma_bf16(C[nt], al, bh);
        }
    }

    // ---- store ------------------------------------------------------------
#pragma unroll
    for (int nt = 0; nt < 16; nt++) {
        int d0 = nt * 8 + tc * 2;
        *reinterpret_cast<float2*>(op + (wrow + g) * 128 + d0) =
            make_float2(C[nt][0], C[nt][1]);
        *reinterpret_cast<float2*>(op + (wrow + g + 8) * 128 + d0) =
            make_float2(C[nt][2], C[nt][3]);
    }
}

// ---------------- launch ----------------------------------------------------
extern "C" void kernel_launch(void* const* d_in, const int* in_sizes, int n_in,
                              void* d_out, int out_size) {
    const float* q     = (const float*)d_in[0];
    const float* k     = (const float*)d_in[1];
    const float* h     = (const float*)d_in[2];
    const float* gamma = (const float*)d_in[3];
    float* out = (float*)d_out;

    cudaFuncSetAttribute(s_kernel, cudaFuncAttributeMaxDynamicSharedMemorySize,
                         SMEM_BYTES);
    cudaFuncSetAttribute(out_kernel, cudaFuncAttributeMaxDynamicSharedMemorySize,
                         SMEM_BYTES);

    pow_kernel<<<BLKSZ + 1, RDIM>>>(gamma);
    s_kernel<<<NTILE, 256, SMEM_BYTES>>>(k, h);
    scan_kernel<<<dim3(RDIM, BATCH), DDIM>>>();
    out_kernel<<<NTILE, 256, SMEM_BYTES>>>(q, k, h, out);
}

// round 6
// speedup vs baseline: 2.3456x; 1.1042x over previous
#include <cuda_runtime.h>
#include <cuda_bf16.h>
#include <math.h>
#include <stdint.h>

#define BATCH 8
#define WIN   4096
#define RDIM  128
#define DDIM  128
#define BLKSZ 128
#define NBLK  (WIN / BLKSZ)   // 32
#define NTILE (BATCH * NBLK)  // 256

// ---------------- scratch (device globals) ----------------------------------
__device__ float g_pow[(BLKSZ + 1) * RDIM];   // pow[n][r] = gamma_r^n
__device__ float g_ipow[BLKSZ * RDIM];        // ipow[n][r] = gamma_r^{-n}
__device__ float g_S[NTILE * RDIM * DDIM];
__device__ float g_state[NTILE * RDIM * DDIM];

// ---------------- smem matrix layout -----------------------------------------
// split bf16 matrix, natural row-major: hi half then lo half.
// each half: 128 rows x 128 bf16, row padded to 68 words (136B).
// banks for 16B segments: (4*row + seg) -> conflict-free ldmatrix phases.
#define SROW_W 68
#define ROWB   (SROW_W * 4)          // 272 bytes
#define HALF_W (128 * SROW_W)
#define HALF_B (HALF_W * 4)          // 34816 bytes (16B aligned)
#define MAT_W  (2 * HALF_W)
#define SMEM_BYTES (MAT_W * 4)       // 69632 B -> 2 CTAs/SM

// ---------------- helpers ----------------------------------------------------
__device__ __forceinline__ uint32_t pkbf(float a, float b) {
    __nv_bfloat162 t = __floats2bfloat162_rn(a, b);
    return *reinterpret_cast<uint32_t*>(&t);
}
__device__ __forceinline__ void split1(float v, float& hi, float& lo) {
    __nv_bfloat16 h = __float2bfloat16(v);
    hi = __bfloat162float(h);
    lo = v - hi;
}
__device__ __forceinline__ void split2(float a, float b, uint32_t& ph, uint32_t& pl) {
    float h0, l0, h1, l1;
    split1(a, h0, l0);
    split1(b, h1, l1);
    ph = pkbf(h0, h1);
    pl = pkbf(l0, l1);
}
__device__ __forceinline__ void mma_bf16(float* c, const uint32_t* a, const uint32_t* b) {
    asm volatile(
        "mma.sync.aligned.m16n8k16.row.col.f32.bf16.bf16.f32 "
        "{%0,%1,%2,%3}, {%4,%5,%6,%7}, {%8,%9}, {%0,%1,%2,%3};"
        : "+f"(c[0]), "+f"(c[1]), "+f"(c[2]), "+f"(c[3])
        : "r"(a[0]), "r"(a[1]), "r"(a[2]), "r"(a[3]), "r"(b[0]), "r"(b[1]));
}
__device__ __forceinline__ void ldsm_x4(uint32_t* r, uint32_t a) {
    asm volatile("ldmatrix.sync.aligned.m8n8.x4.shared.b16 {%0,%1,%2,%3}, [%4];"
        : "=r"(r[0]), "=r"(r[1]), "=r"(r[2]), "=r"(r[3]) : "r"(a));
}
__device__ __forceinline__ void ldsm_x4_t(uint32_t* r, uint32_t a) {
    asm volatile("ldmatrix.sync.aligned.m8n8.x4.trans.shared.b16 {%0,%1,%2,%3}, [%4];"
        : "=r"(r[0]), "=r"(r[1]), "=r"(r[2]), "=r"(r[3]) : "r"(a));
}

// A fragment streamed from global, natural layout: A[i][r] = src[i][r]*scl[i][r]
__device__ __forceinline__ void ldA_nat(uint32_t* ah, uint32_t* al,
                                        const float* base, const float* sclb,
                                        int kt, int lane) {
    int g = lane >> 2, tc = lane & 3;
    int c = kt * 16 + tc * 2;
    const float* p = base + g * 128 + c;
    const float* w = sclb + g * 128 + c;
    float2 v0 = *(const float2*)(p);
    float2 s0 = *(const float2*)(w);
    float2 v1 = *(const float2*)(p + 8);
    float2 s1 = *(const float2*)(w + 8);
    float2 v2 = *(const float2*)(p + 8 * 128);
    float2 s2 = *(const float2*)(w + 8 * 128);
    float2 v3 = *(const float2*)(p + 8 * 128 + 8);
    float2 s3 = *(const float2*)(w + 8 * 128 + 8);
    split2(v0.x * s0.x, v0.y * s0.y, ah[0], al[0]);
    split2(v2.x * s2.x, v2.y * s2.y, ah[1], al[1]);
    split2(v1.x * s1.x, v1.y * s1.y, ah[2], al[2]);
    split2(v3.x * s3.x, v3.y * s3.y, ah[3], al[3]);
}

// A fragment streamed from global, transposed+scaled (s_kernel):
// A[r][j] = k[j*128 + r] * g_pow[(127-j)*128 + r]
__device__ __forceinline__ float ktr_elem(const float* kb, int j, int r) {
    return kb[j * 128 + r] * g_pow[(127 - j) * 128 + r];
}
__device__ __forceinline__ void ldA_ktr(uint32_t* ah, uint32_t* al,
                                        const float* kb, int mrow, int kt, int lane) {
    int g = lane >> 2, tc = lane & 3;
    int r = mrow + g;
    int j = kt * 16 + tc * 2;
    split2(ktr_elem(kb, j,     r),     ktr_elem(kb, j + 1, r),     ah[0], al[0]);
    split2(ktr_elem(kb, j,     r + 8), ktr_elem(kb, j + 1, r + 8), ah[1], al[1]);
    split2(ktr_elem(kb, j + 8, r),     ktr_elem(kb, j + 9, r),     ah[2], al[2]);
    split2(ktr_elem(kb, j + 8, r + 8), ktr_elem(kb, j + 9, r + 8), ah[3], al[3]);
}

// scale+split+store, natural layout (no syncs)
__device__ __forceinline__ void build_scaled(const float* __restrict__ src,
                                             const float* __restrict__ scl,
                                             uint32_t* __restrict__ mat, int tid) {
#pragma unroll 4
    for (int p = tid; p < 8192; p += 256) {
        int i = p >> 6, cp = p & 63;
        float2 v = *reinterpret_cast<const float2*>(src + i * 128 + cp * 2);
        float2 s = *reinterpret_cast<const float2*>(scl + i * 128 + cp * 2);
        uint32_t ph, pl;
        split2(v.x * s.x, v.y * s.y, ph, pl);
        int w = i * SROW_W + cp;
        mat[w] = ph;
        mat[w + HALF_W] = pl;
    }
}
// copy+split+store, natural layout (no syncs)
__device__ __forceinline__ void build_copy(const float* __restrict__ src,
                                           uint32_t* __restrict__ mat, int tid) {
#pragma unroll 4
    for (int p = tid; p < 8192; p += 256) {
        int i = p >> 6, cp = p & 63;
        float2 v = *reinterpret_cast<const float2*>(src + i * 128 + cp * 2);
        uint32_t ph, pl;
        split2(v.x, v.y, ph, pl);
        int w = i * SROW_W + cp;
        mat[w] = ph;
        mat[w + HALF_W] = pl;
    }
}

// ---------------- kernel 0: decay power tables ------------------------------
__global__ void pow_kernel(const float* __restrict__ gamma) {
    int n = blockIdx.x;
    int r = threadIdx.x;
    float g = fmaxf(gamma[r], 1e-8f);
    float lg = logf(g);
    g_pow[n * RDIM + r] = expf((float)n * lg);
    if (n < BLKSZ) g_ipow[n * RDIM + r] = expf(-(float)n * lg);
}

// ---------------- kernel 1: S[r,d] = sum_j gamma^{127-j} k[j,r] h[j,d] ------
// B = H natural [j][d] = [k][n] -> trans LDSM ; A = K2^T streamed from global
__global__ __launch_bounds__(256, 2)
void s_kernel(const float* __restrict__ k, const float* __restrict__ h) {
    extern __shared__ uint32_t smw[];
    uint32_t* M = smw;

    int tid = threadIdx.x;
    int lane = tid & 31, wid = tid >> 5;
    int wrow = wid * 16;
    int bn = blockIdx.x;
    int b = bn / NBLK, n = bn % NBLK;
    const float* kp = k + ((size_t)b * WIN + (size_t)n * BLKSZ) * RDIM;
    const float* hp = h + ((size_t)b * WIN + (size_t)n * BLKSZ) * DDIM;
    float* Sp = g_S + (size_t)bn * RDIM * DDIM;

    build_copy(hp, M, tid);
    __syncthreads();

    uint32_t sb = (uint32_t)__cvta_generic_to_shared(M);
    int lrow = lane & 7, seg = lane >> 3;
    uint32_t off_t = (uint32_t)((((seg & 1) << 3) + lrow) * ROWB + (((seg >> 1) << 3) << 1));

    float C[16][4];
#pragma unroll
    for (int nt = 0; nt < 16; nt++)
#pragma unroll
        for (int v = 0; v < 4; v++) C[nt][v] = 0.f;

#pragma unroll 2
    for (int kt = 0; kt < 8; kt++) {
        uint32_t ah[4], al[4];
        ldA_ktr(ah, al, kp, wrow, kt, lane);
        uint32_t kb = sb + (uint32_t)(kt * 16) * ROWB + off_t;
#pragma unroll
        for (int p = 0; p < 8; p++) {
            uint32_t bh[4], bl[4];
            ldsm_x4_t(bh, kb + p * 32);
            ldsm_x4_t(bl, kb + p * 32 + HALF_B);
            mma_bf16(C[2 * p],     ah, bh);
            mma_bf16(C[2 * p],     ah, bl);
            mma_bf16(C[2 * p],     al, bh);
            mma_bf16(C[2 * p + 1], ah, bh + 2);
            mma_bf16(C[2 * p + 1], ah, bl + 2);
            mma_bf16(C[2 * p + 1], al, bh + 2);
        }
    }

    int g = lane >> 2, tc = lane & 3;
#pragma unroll
    for (int nt = 0; nt < 16; nt++) {
        int d0 = nt * 8 + tc * 2;
        *reinterpret_cast<float2*>(Sp + (wrow + g) * 128 + d0) =
            make_float2(C[nt][0], C[nt][1]);
        *reinterpret_cast<float2*>(Sp + (wrow + g + 8) * 128 + d0) =
            make_float2(C[nt][2], C[nt][3]);
    }
}

// ---------------- kernel 2: elementwise scan over blocks --------------------
__global__ void scan_kernel() {
    int r = blockIdx.x, b = blockIdx.y, d = threadIdx.x;
    float g = g_pow[BLKSZ * RDIM + r];
    float s = 0.f;
    size_t base = ((size_t)b * NBLK) * RDIM * DDIM + (size_t)r * DDIM + d;
#pragma unroll 4
    for (int n = 0; n < NBLK; n++) {
        size_t off = base + (size_t)n * RDIM * DDIM;
        g_state[off] = s;
        s = fmaf(g, s, g_S[off]);
    }
}

// ---------------- kernel 3: per-tile output ---------------------------------
__global__ __launch_bounds__(256, 2)
void out_kernel(const float* __restrict__ q, const float* __restrict__ kk,
                const float* __restrict__ h, float* __restrict__ out) {
    extern __shared__ uint32_t smw[];
    uint32_t* M = smw;                 // Khat -> H -> state (all natural layout)

    int tid = threadIdx.x;
    int lane = tid & 31, wid = tid >> 5;
    int wrow = wid * 16;
    int g = lane >> 2, tc = lane & 3;
    int bn = blockIdx.x;
    int b = bn / NBLK, n = bn % NBLK;
    const float* qp = q  + ((size_t)b * WIN + (size_t)n * BLKSZ) * RDIM;
    const float* kp = kk + ((size_t)b * WIN + (size_t)n * BLKSZ) * RDIM;
    const float* hp = h  + ((size_t)b * WIN + (size_t)n * BLKSZ) * DDIM;
    const float* st = g_state + (size_t)bn * RDIM * DDIM;
    float* op = out + ((size_t)b * WIN + (size_t)n * BLKSZ) * DDIM;

    const float* qwp = qp + wrow * 128;
    const float* pw0 = g_pow + wrow * RDIM;
    const float* pw1 = g_pow + (wrow + 1) * RDIM;

    uint32_t sb = (uint32_t)__cvta_generic_to_shared(M);
    int lrow = lane & 7, seg = lane >> 3;
    // non-trans offsets (storage [n][k]): row = lrow + (seg>>1)*8, col16B = seg&1
    uint32_t off_n = (uint32_t)(((lrow + ((seg >> 1) << 3)) * ROWB) + ((seg & 1) << 4));
    // trans offsets (storage [k][n]): row = lrow + (seg&1)*8, colbyte = (seg>>1)*16
    uint32_t off_t = (uint32_t)((((seg & 1) << 3) + lrow) * ROWB + (((seg >> 1) << 3) << 1));

    // ---- build Khat = k * g^-j, natural [j][r] ---------------------------
    build_scaled(kp, g_ipow, M, tid);
    __syncthreads();

    // ---- GEMM1: P = Qhat @ Khat^T  (A streamed; B non-trans LDSM) --------
    float P[16][4];
#pragma unroll
    for (int nt = 0; nt < 16; nt++)
#pragma unroll
        for (int v = 0; v < 4; v++) P[nt][v] = 0.f;

#pragma unroll 2
    for (int kt = 0; kt < 8; kt++) {
        uint32_t ah[4], al[4];
        ldA_nat(ah, al, qwp, pw0, kt, lane);
        uint32_t kb = sb + (uint32_t)(kt * 32) + off_n;
#pragma unroll
        for (int p = 0; p < 8; p++) {
            if (p > wid) break;                 // causal: nt pairs 0..wid
            uint32_t bh[4], bl[4];
            ldsm_x4(bh, kb + (uint32_t)(p * 16) * ROWB);
            ldsm_x4(bl, kb + (uint32_t)(p * 16) * ROWB + HALF_B);
            mma_bf16(P[2 * p],     ah, bh);
            mma_bf16(P[2 * p],     ah, bl);
            mma_bf16(P[2 * p],     al, bh);
            mma_bf16(P[2 * p + 1], ah, bh + 2);
            mma_bf16(P[2 * p + 1], ah, bl + 2);
            mma_bf16(P[2 * p + 1], al, bh + 2);
        }
    }

    // ---- causal mask + split P into A-fragments (registers) --------------
    uint32_t pah[8][4], pal[8][4];
#pragma unroll
    for (int nt = 0; nt < 16; nt++) {
        int jb = nt * 8 + tc * 2;
        int i0 = wrow + g, i1 = i0 + 8;
        float c0 = (jb     <= i0) ? P[nt][0] : 0.f;
        float c1 = (jb + 1 <= i0) ? P[nt][1] : 0.f;
        float c2 = (jb     <= i1) ? P[nt][2] : 0.f;
        float c3 = (jb + 1 <= i1) ? P[nt][3] : 0.f;
        int kt = nt >> 1, s = (nt & 1) * 2;
        split2(c0, c1, pah[kt][s],     pal[kt][s]);
        split2(c2, c3, pah[kt][s + 1], pal[kt][s + 1]);
    }

    // ---- rebuild M <- H natural [j][d] -----------------------------------
    __syncthreads();
    build_copy(hp, M, tid);
    __syncthreads();

    // ---- GEMM2: C = P @ H  (A regs; B trans LDSM); skip kt > wid ---------
    float C[16][4];
#pragma unroll
    for (int nt = 0; nt < 16; nt++)
#pragma unroll
        for (int v = 0; v < 4; v++) C[nt][v] = 0.f;
#pragma unroll
    for (int kt = 0; kt < 8; kt++) {
        if (kt > wid) break;
        uint32_t kb = sb + (uint32_t)(kt * 16) * ROWB + off_t;
#pragma unroll
        for (int p = 0; p < 8; p++) {
            uint32_t bh[4], bl[4];
            ldsm_x4_t(bh, kb + p * 32);
            ldsm_x4_t(bl, kb + p * 32 + HALF_B);
            mma_bf16(C[2 * p],     pah[kt], bh);
            mma_bf16(C[2 * p],     pah[kt], bl);
            mma_bf16(C[2 * p],     pal[kt], bh);
            mma_bf16(C[2 * p + 1], pah[kt], bh + 2);
            mma_bf16(C[2 * p + 1], pah[kt], bl + 2);
            mma_bf16(C[2 * p + 1], pal[kt], bh + 2);
        }
    }

    // ---- rebuild M <- state natural [r][d] -------------------------------
    __syncthreads();
    build_copy(st, M, tid);
    __syncthreads();

    // ---- GEMM3: C += Qtilde @ state (A streamed; B trans LDSM) -----------
#pragma unroll 2
    for (int kt = 0; kt < 8; kt++) {
        uint32_t ah[4], al[4];
        ldA_nat(ah, al, qwp, pw1, kt, lane);
        uint32_t kb = sb + (uint32_t)(kt * 16) * ROWB + off_t;
#pragma unroll
        for (int p = 0; p < 8; p++) {
            uint32_t bh[4], bl[4];
            ldsm_x4_t(bh, kb + p * 32);
            ldsm_x4_t(bl, kb + p * 32 + HALF_B);
            mma_bf16(C[2 * p],     ah, bh);
            mma_bf16(C[2 * p],     ah, bl);
            mma_bf16(C[2 * p],     al, bh);
            mma_bf16(C[2 * p + 1], ah, bh + 2);
            mma_bf16(C[2 * p + 1], ah, bl + 2);
            mma_bf16(C[2 * p + 1], al, bh + 2);
        }
    }

    // ---- store ------------------------------------------------------------
#pragma unroll
    for (int nt = 0; nt < 16; nt++) {
        int d0 = nt * 8 + tc * 2;
        *reinterpret_cast<float2*>(op + (wrow + g) * 128 + d0) =
            make_float2(C[nt][0], C[nt][1]);
        *reinterpret_cast<float2*>(op + (wrow + g + 8) * 128 + d0) =
            make_float2(C[nt][2], C[nt][3]);
    }
}

// ---------------- launch ----------------------------------------------------
extern "C" void kernel_launch(void* const* d_in, const int* in_sizes, int n_in,
                              void* d_out, int out_size) {
    const float* q     = (const float*)d_in[0];
    const float* k     = (const float*)d_in[1];
    const float* h     = (const float*)d_in[2];
    const float* gamma = (const float*)d_in[3];
    float* out = (float*)d_out;

    cudaFuncSetAttribute(s_kernel, cudaFuncAttributeMaxDynamicSharedMemorySize,
                         SMEM_BYTES);
    cudaFuncSetAttribute(out_kernel, cudaFuncAttributeMaxDynamicSharedMemorySize,
                         SMEM_BYTES);

    pow_kernel<<<BLKSZ + 1, RDIM>>>(gamma);
    s_kernel<<<NTILE, 256, SMEM_BYTES>>>(k, h);
    scan_kernel<<<dim3(RDIM, BATCH), DDIM>>>();
    out_kernel<<<NTILE, 256, SMEM_BYTES>>>(q, k, h, out);
}